// round 3
// baseline (speedup 1.0000x reference)
#include <cuda_runtime.h>

#define NNODES 20000
#define NEDGES 320000
#define DIM    512

// Scratch (allocation-free rule: __device__ globals)
__device__ float g_h[(size_t)NNODES * DIM];   // GEMM output h = x @ W
__device__ float g_a[(size_t)NNODES * DIM];   // aggregation accumulator
__device__ float g_dinv[NNODES];
__device__ int   g_deg[NNODES];
__device__ int   g_src[NEDGES];
__device__ int   g_dst[NEDGES];
__device__ int   g_is_i32;   // nonzero -> edge_index buffer is int32

// ---------------------------------------------------------------------------
// Edge index normalization: detect int32 vs int64 layout, extract to int
// ---------------------------------------------------------------------------
__global__ void flag_init_kernel() { g_is_i32 = 0; }

__global__ void dtype_sniff_kernel(const int* __restrict__ ei32) {
    // OR together odd-position words: all-zero <=> int64 layout (high words)
    int i = blockIdx.x * blockDim.x + threadIdx.x;  // 0 .. E-1
    int acc = 0;
    if (i < NEDGES) acc = ei32[2 * i + 1];
#pragma unroll
    for (int o = 16; o > 0; o >>= 1) acc |= __shfl_xor_sync(0xffffffffu, acc, o);
    if ((threadIdx.x & 31) == 0 && acc != 0) atomicOr(&g_is_i32, 1);
}

__global__ void edge_convert_kernel(const void* __restrict__ ei) {
    int i = blockIdx.x * blockDim.x + threadIdx.x;  // 0 .. 2E-1
    if (i >= 2 * NEDGES) return;
    int v;
    if (g_is_i32) v = ((const int*)ei)[i];
    else          v = (int)((const long long*)ei)[i];
    if (i < NEDGES) g_src[i] = v;
    else            g_dst[i - NEDGES] = v;
}

// ---------------------------------------------------------------------------
// Degree / normalization
// ---------------------------------------------------------------------------
__global__ void deg_init_kernel() {
    int i = blockIdx.x * blockDim.x + threadIdx.x;
    if (i < NNODES) g_deg[i] = 1;  // self-loop
}

__global__ void deg_count_kernel() {
    int e = blockIdx.x * blockDim.x + threadIdx.x;
    if (e < NEDGES) atomicAdd(&g_deg[g_dst[e]], 1);
}

__global__ void dinv_kernel() {
    int i = blockIdx.x * blockDim.x + threadIdx.x;
    if (i < NNODES) g_dinv[i] = rsqrtf((float)g_deg[i]);
}

// ---------------------------------------------------------------------------
// GEMM: C[M, 512] = op(A)[M, 512] @ B[512, 512]
// MODE 0: A = Aparam (raw),                 C = g_h
// MODE 1: A = g_a with relu(a + bias[k]),   C = g_h
// 128x128 tile, BK=16, 256 threads, 8x8 per thread.
// ---------------------------------------------------------------------------
template <int MODE>
__global__ void __launch_bounds__(256, 2)
gemm512_kernel(const float* __restrict__ Aparam,
               const float* __restrict__ B,
               const float* __restrict__ bias) {
    const int BM = 128, BN = 128, BK = 16;
    __shared__ float As[BK][BM + 4];
    __shared__ float Bs[BK][BN];

    const float* A = (MODE == 0) ? Aparam : g_a;
    float* C = g_h;

    int tid  = threadIdx.x;
    int row0 = blockIdx.y * BM;
    int col0 = blockIdx.x * BN;

    int tx = tid & 15;       // 0..15 -> N direction (8 cols each)
    int ty = tid >> 4;       // 0..15 -> M direction (8 rows each)

    // A load mapping: 128 rows x 16 cols = 512 float4; 2 per thread
    int a_row  = tid >> 2;   // 0..63, + 64 on second pass
    int a_col4 = tid & 3;    // 0..3  -> col = a_col4*4
    // B load mapping: 16 rows x 128 cols = 512 float4; 2 per thread
    int b_row  = tid >> 5;   // 0..7, + 8 on second pass
    int b_col4 = tid & 31;   // 0..31 -> col = b_col4*4

    float acc[8][8];
#pragma unroll
    for (int i = 0; i < 8; i++)
#pragma unroll
        for (int j = 0; j < 8; j++) acc[i][j] = 0.f;

    for (int k0 = 0; k0 < DIM; k0 += BK) {
        // ---- load A tile (transposed into As[k][m]) ----
#pragma unroll
        for (int p = 0; p < 2; p++) {
            int r    = a_row + p * 64;
            int grow = row0 + r;
            int kc   = k0 + a_col4 * 4;
            float4 v = make_float4(0.f, 0.f, 0.f, 0.f);
            if (grow < NNODES)
                v = *(const float4*)&A[(size_t)grow * DIM + kc];
            if (MODE == 1) {
                v.x = fmaxf(v.x + bias[kc + 0], 0.f);
                v.y = fmaxf(v.y + bias[kc + 1], 0.f);
                v.z = fmaxf(v.z + bias[kc + 2], 0.f);
                v.w = fmaxf(v.w + bias[kc + 3], 0.f);
                if (grow >= NNODES) { v.x = v.y = v.z = v.w = 0.f; }
            }
            As[a_col4 * 4 + 0][r] = v.x;
            As[a_col4 * 4 + 1][r] = v.y;
            As[a_col4 * 4 + 2][r] = v.z;
            As[a_col4 * 4 + 3][r] = v.w;
        }
        // ---- load B tile ----
#pragma unroll
        for (int p = 0; p < 2; p++) {
            int r = b_row + p * 8;
            float4 v = *(const float4*)&B[(size_t)(k0 + r) * DIM + col0 + b_col4 * 4];
            *(float4*)&Bs[r][b_col4 * 4] = v;
        }
        __syncthreads();

#pragma unroll
        for (int k = 0; k < BK; k++) {
            float ra[8], rb[8];
#pragma unroll
            for (int i = 0; i < 8; i++) ra[i] = As[k][ty * 8 + i];
#pragma unroll
            for (int j = 0; j < 8; j++) rb[j] = Bs[k][tx * 8 + j];
#pragma unroll
            for (int i = 0; i < 8; i++)
#pragma unroll
                for (int j = 0; j < 8; j++)
                    acc[i][j] = fmaf(ra[i], rb[j], acc[i][j]);
        }
        __syncthreads();
    }

    // ---- store ----
#pragma unroll
    for (int i = 0; i < 8; i++) {
        int grow = row0 + ty * 8 + i;
        if (grow < NNODES) {
#pragma unroll
            for (int j = 0; j < 8; j += 4) {
                float4 v = make_float4(acc[i][j], acc[i][j + 1],
                                       acc[i][j + 2], acc[i][j + 3]);
                *(float4*)&C[(size_t)grow * DIM + col0 + tx * 8 + j] = v;
            }
        }
    }
}

// ---------------------------------------------------------------------------
// Aggregation: self-loop init  a[i,:] = h[i,:] * dinv[i]^2
// ---------------------------------------------------------------------------
__global__ void agg_self_kernel() {
    size_t idx = (size_t)blockIdx.x * blockDim.x + threadIdx.x;
    size_t total = (size_t)NNODES * (DIM / 4);
    if (idx >= total) return;
    int row = (int)(idx >> 7);  // DIM/4 = 128 float4 per row
    float w = g_dinv[row];
    w *= w;
    float4 v = ((const float4*)g_h)[idx];
    v.x *= w; v.y *= w; v.z *= w; v.w *= w;
    ((float4*)g_a)[idx] = v;
}

// ---------------------------------------------------------------------------
// Aggregation: edges  a[dst,:] += h[src,:] * dinv[src]*dinv[dst]
// one warp per edge, float4 gather + 4 scalar REDG.ADD.F32 per vec
// ---------------------------------------------------------------------------
__global__ void agg_edges_kernel() {
    int warp = (blockIdx.x * blockDim.x + threadIdx.x) >> 5;
    int lane = threadIdx.x & 31;
    if (warp >= NEDGES) return;
    int s = g_src[warp];
    int d = g_dst[warp];
    float w = g_dinv[s] * g_dinv[d];
    const float4* hs = (const float4*)(g_h + (size_t)s * DIM);
    float* ad = g_a + (size_t)d * DIM;
#pragma unroll
    for (int i = 0; i < 4; i++) {
        int c4 = lane + 32 * i;
        float4 v = hs[c4];
        atomicAdd(&ad[4 * c4 + 0], v.x * w);
        atomicAdd(&ad[4 * c4 + 1], v.y * w);
        atomicAdd(&ad[4 * c4 + 2], v.z * w);
        atomicAdd(&ad[4 * c4 + 3], v.w * w);
    }
}

// ---------------------------------------------------------------------------
// Output init + max pool: out[j] = max_i relu(a[i,j] + b2[j])
// ---------------------------------------------------------------------------
__global__ void out_init_kernel(float* out) {
    int j = threadIdx.x;
    if (j < DIM) out[j] = 0.0f;  // relu output >= 0, so 0 is a valid floor
}

#define POOL_ROWS 100
__global__ void maxpool_kernel(const float* __restrict__ b2, float* __restrict__ out) {
    int col  = threadIdx.x;   // 512 threads
    int row0 = blockIdx.x * POOL_ROWS;
    float bb = b2[col];
    float m = 0.f;
#pragma unroll 4
    for (int r = 0; r < POOL_ROWS; r++) {
        int row = row0 + r;
        if (row >= NNODES) break;
        float v = g_a[(size_t)row * DIM + col] + bb;
        m = fmaxf(m, fmaxf(v, 0.f));
    }
    // all values >= 0 -> int-reinterpreted compare is order-preserving
    atomicMax((int*)out + col, __float_as_int(m));
}

// ---------------------------------------------------------------------------
extern "C" void kernel_launch(void* const* d_in, const int* in_sizes, int n_in,
                              void* d_out, int out_size) {
    const float* X  = (const float*)d_in[0];
    const void*  ei = d_in[1];
    // d_in[2] = edge_attr (unused by GCNConv)
    const float* W1 = (const float*)d_in[3];
    const float* b1 = (const float*)d_in[4];
    const float* W2 = (const float*)d_in[5];
    const float* b2 = (const float*)d_in[6];
    float* out = (float*)d_out;

    // ---- edge index normalization (int32 vs int64 sniff + convert) ----
    flag_init_kernel<<<1, 1>>>();
    dtype_sniff_kernel<<<(NEDGES + 255) / 256, 256>>>((const int*)ei);
    edge_convert_kernel<<<(2 * NEDGES + 255) / 256, 256>>>(ei);

    // ---- normalization ----
    deg_init_kernel<<<(NNODES + 255) / 256, 256>>>();
    deg_count_kernel<<<(NEDGES + 255) / 256, 256>>>();
    dinv_kernel<<<(NNODES + 255) / 256, 256>>>();

    dim3 gemm_grid(DIM / 128, (NNODES + 127) / 128);

    int self_blocks = (int)(((size_t)NNODES * (DIM / 4) + 255) / 256);
    int edge_blocks = NEDGES / 8;  // 8 warps/block, 1 warp/edge

    // ---- layer 1: h = X @ W1 ; a = A_norm h ----
    gemm512_kernel<0><<<gemm_grid, 256>>>(X, W1, nullptr);
    agg_self_kernel<<<self_blocks, 256>>>();
    agg_edges_kernel<<<edge_blocks, 256>>>();

    // ---- layer 2: h = relu(a + b1) @ W2 ; a = A_norm h ----
    gemm512_kernel<1><<<gemm_grid, 256>>>(nullptr, W2, b1);
    agg_self_kernel<<<self_blocks, 256>>>();
    agg_edges_kernel<<<edge_blocks, 256>>>();

    // ---- global max pool over relu(a + b2) ----
    out_init_kernel<<<1, DIM>>>(out);
    maxpool_kernel<<<(NNODES + POOL_ROWS - 1) / POOL_ROWS, DIM>>>(b2, out);
}

// round 4
// speedup vs baseline: 1.8396x; 1.8396x over previous
#include <cuda_runtime.h>

#define NNODES 20000
#define NEDGES 320000
#define DIM    512

// Scratch (allocation-free rule: __device__ globals)
__device__ float g_h[(size_t)NNODES * DIM];   // GEMM output h = x @ W
__device__ float g_a[(size_t)NNODES * DIM];   // aggregation result
__device__ float g_dinv[NNODES];
__device__ int   g_deg[NNODES];
__device__ int   g_src[NEDGES];
__device__ int   g_dst[NEDGES];
__device__ int   g_is_i32;            // nonzero -> edge_index buffer is int32
__device__ int   g_rowptr[NNODES + 1];
__device__ int   g_cursor[NNODES];
__device__ int   g_csr_src[NEDGES];
__device__ float g_csr_w[NEDGES];

// ---------------------------------------------------------------------------
// Edge index normalization: detect int32 vs int64 layout, extract to int
// ---------------------------------------------------------------------------
__global__ void flag_init_kernel() { g_is_i32 = 0; }

__global__ void dtype_sniff_kernel(const int* __restrict__ ei32) {
    // OR together odd-position words: all-zero <=> int64 layout (high words)
    int i = blockIdx.x * blockDim.x + threadIdx.x;  // 0 .. E-1
    int acc = 0;
    if (i < NEDGES) acc = ei32[2 * i + 1];
#pragma unroll
    for (int o = 16; o > 0; o >>= 1) acc |= __shfl_xor_sync(0xffffffffu, acc, o);
    if ((threadIdx.x & 31) == 0 && acc != 0) atomicOr(&g_is_i32, 1);
}

__global__ void edge_convert_kernel(const void* __restrict__ ei) {
    int i = blockIdx.x * blockDim.x + threadIdx.x;  // 0 .. 2E-1
    if (i >= 2 * NEDGES) return;
    int v;
    if (g_is_i32) v = ((const int*)ei)[i];
    else          v = (int)((const long long*)ei)[i];
    if (i < NEDGES) g_src[i] = v;
    else            g_dst[i - NEDGES] = v;
}

// ---------------------------------------------------------------------------
// Degree / normalization
// ---------------------------------------------------------------------------
__global__ void deg_init_kernel() {
    int i = blockIdx.x * blockDim.x + threadIdx.x;
    if (i < NNODES) g_deg[i] = 1;  // self-loop
}

__global__ void deg_count_kernel() {
    int e = blockIdx.x * blockDim.x + threadIdx.x;
    if (e < NEDGES) atomicAdd(&g_deg[g_dst[e]], 1);
}

__global__ void dinv_kernel() {
    int i = blockIdx.x * blockDim.x + threadIdx.x;
    if (i < NNODES) g_dinv[i] = rsqrtf((float)g_deg[i]);
}

// ---------------------------------------------------------------------------
// Exclusive prefix scan of in-degree (deg-1) -> rowptr, cursor. 1 block.
// ---------------------------------------------------------------------------
#define SCAN_T 1024
__global__ void scan_kernel() {
    __shared__ int sums[SCAN_T];
    const int CH = (NNODES + SCAN_T - 1) / SCAN_T;  // 20
    int t = threadIdx.x;
    int base = t * CH;
    int local = 0;
#pragma unroll
    for (int i = 0; i < CH; i++) {
        int idx = base + i;
        if (idx < NNODES) local += g_deg[idx] - 1;
    }
    sums[t] = local;
    __syncthreads();
    // inclusive Hillis-Steele scan
    for (int o = 1; o < SCAN_T; o <<= 1) {
        int v = (t >= o) ? sums[t - o] : 0;
        __syncthreads();
        sums[t] += v;
        __syncthreads();
    }
    int run = (t > 0) ? sums[t - 1] : 0;
#pragma unroll
    for (int i = 0; i < CH; i++) {
        int idx = base + i;
        if (idx < NNODES) {
            g_rowptr[idx] = run;
            g_cursor[idx] = run;
            run += g_deg[idx] - 1;
        }
    }
    if (t == SCAN_T - 1) g_rowptr[NNODES] = sums[SCAN_T - 1];
}

// ---------------------------------------------------------------------------
// Scatter edges into CSR (by dst), precomputing edge weight
// ---------------------------------------------------------------------------
__global__ void scatter_kernel() {
    int e = blockIdx.x * blockDim.x + threadIdx.x;
    if (e >= NEDGES) return;
    int s = g_src[e];
    int d = g_dst[e];
    int pos = atomicAdd(&g_cursor[d], 1);
    g_csr_src[pos] = s;
    g_csr_w[pos] = g_dinv[s] * g_dinv[d];
}

// ---------------------------------------------------------------------------
// GEMM: C[M, 512] = op(A)[M, 512] @ B[512, 512]
// MODE 0: A = Aparam (raw),                 C = g_h
// MODE 1: A = g_a with relu(a + bias[k]),   C = g_h
// 128x128 tile, BK=16, 256 threads, 8x8 per thread.
// ---------------------------------------------------------------------------
template <int MODE>
__global__ void __launch_bounds__(256, 2)
gemm512_kernel(const float* __restrict__ Aparam,
               const float* __restrict__ B,
               const float* __restrict__ bias) {
    const int BM = 128, BN = 128, BK = 16;
    __shared__ float As[BK][BM + 4];
    __shared__ float Bs[BK][BN];

    const float* A = (MODE == 0) ? Aparam : g_a;
    float* C = g_h;

    int tid  = threadIdx.x;
    int row0 = blockIdx.y * BM;
    int col0 = blockIdx.x * BN;

    int tx = tid & 15;       // 0..15 -> N direction (8 cols each)
    int ty = tid >> 4;       // 0..15 -> M direction (8 rows each)

    int a_row  = tid >> 2;   // 0..63, + 64 on second pass
    int a_col4 = tid & 3;    // 0..3  -> col = a_col4*4
    int b_row  = tid >> 5;   // 0..7, + 8 on second pass
    int b_col4 = tid & 31;   // 0..31 -> col = b_col4*4

    float acc[8][8];
#pragma unroll
    for (int i = 0; i < 8; i++)
#pragma unroll
        for (int j = 0; j < 8; j++) acc[i][j] = 0.f;

    for (int k0 = 0; k0 < DIM; k0 += BK) {
        // ---- load A tile (transposed into As[k][m]) ----
#pragma unroll
        for (int p = 0; p < 2; p++) {
            int r    = a_row + p * 64;
            int grow = row0 + r;
            int kc   = k0 + a_col4 * 4;
            float4 v = make_float4(0.f, 0.f, 0.f, 0.f);
            if (grow < NNODES)
                v = *(const float4*)&A[(size_t)grow * DIM + kc];
            if (MODE == 1) {
                v.x = fmaxf(v.x + bias[kc + 0], 0.f);
                v.y = fmaxf(v.y + bias[kc + 1], 0.f);
                v.z = fmaxf(v.z + bias[kc + 2], 0.f);
                v.w = fmaxf(v.w + bias[kc + 3], 0.f);
                if (grow >= NNODES) { v.x = v.y = v.z = v.w = 0.f; }
            }
            As[a_col4 * 4 + 0][r] = v.x;
            As[a_col4 * 4 + 1][r] = v.y;
            As[a_col4 * 4 + 2][r] = v.z;
            As[a_col4 * 4 + 3][r] = v.w;
        }
        // ---- load B tile ----
#pragma unroll
        for (int p = 0; p < 2; p++) {
            int r = b_row + p * 8;
            float4 v = *(const float4*)&B[(size_t)(k0 + r) * DIM + col0 + b_col4 * 4];
            *(float4*)&Bs[r][b_col4 * 4] = v;
        }
        __syncthreads();

#pragma unroll
        for (int k = 0; k < BK; k++) {
            float ra[8], rb[8];
#pragma unroll
            for (int i = 0; i < 8; i++) ra[i] = As[k][ty * 8 + i];
#pragma unroll
            for (int j = 0; j < 8; j++) rb[j] = Bs[k][tx * 8 + j];
#pragma unroll
            for (int i = 0; i < 8; i++)
#pragma unroll
                for (int j = 0; j < 8; j++)
                    acc[i][j] = fmaf(ra[i], rb[j], acc[i][j]);
        }
        __syncthreads();
    }

    // ---- store ----
#pragma unroll
    for (int i = 0; i < 8; i++) {
        int grow = row0 + ty * 8 + i;
        if (grow < NNODES) {
#pragma unroll
            for (int j = 0; j < 8; j += 4) {
                float4 v = make_float4(acc[i][j], acc[i][j + 1],
                                       acc[i][j + 2], acc[i][j + 3]);
                *(float4*)&C[(size_t)grow * DIM + col0 + tx * 8 + j] = v;
            }
        }
    }
}

// ---------------------------------------------------------------------------
// CSR aggregation (atomic-free, self-loop fused):
//   a[d,:] = dinv[d]^2 * h[d,:] + sum_{e: dst=d} w_e * h[src_e,:]
// one 128-thread block per node; each thread owns one float4 of the row.
// ---------------------------------------------------------------------------
__global__ void __launch_bounds__(128)
agg_csr_kernel() {
    int d = blockIdx.x;
    int t = threadIdx.x;  // 0..127 -> float4 column
    const float4* __restrict__ h4 = (const float4*)g_h;

    float dv = g_dinv[d];
    float4 acc = h4[(size_t)d * 128 + t];
    float ws = dv * dv;
    acc.x *= ws; acc.y *= ws; acc.z *= ws; acc.w *= ws;

    int j   = g_rowptr[d];
    int end = g_rowptr[d + 1];

    for (; j + 4 <= end; j += 4) {
        int   s0 = g_csr_src[j],     s1 = g_csr_src[j + 1];
        int   s2 = g_csr_src[j + 2], s3 = g_csr_src[j + 3];
        float w0 = g_csr_w[j],       w1 = g_csr_w[j + 1];
        float w2 = g_csr_w[j + 2],   w3 = g_csr_w[j + 3];
        float4 v0 = h4[(size_t)s0 * 128 + t];
        float4 v1 = h4[(size_t)s1 * 128 + t];
        float4 v2 = h4[(size_t)s2 * 128 + t];
        float4 v3 = h4[(size_t)s3 * 128 + t];
        acc.x += v0.x * w0 + v1.x * w1 + v2.x * w2 + v3.x * w3;
        acc.y += v0.y * w0 + v1.y * w1 + v2.y * w2 + v3.y * w3;
        acc.z += v0.z * w0 + v1.z * w1 + v2.z * w2 + v3.z * w3;
        acc.w += v0.w * w0 + v1.w * w1 + v2.w * w2 + v3.w * w3;
    }
    for (; j < end; j++) {
        int   s = g_csr_src[j];
        float w = g_csr_w[j];
        float4 v = h4[(size_t)s * 128 + t];
        acc.x += v.x * w; acc.y += v.y * w;
        acc.z += v.z * w; acc.w += v.w * w;
    }

    ((float4*)g_a)[(size_t)d * 128 + t] = acc;
}

// ---------------------------------------------------------------------------
// Output init + max pool: out[j] = max_i relu(a[i,j] + b2[j])
// ---------------------------------------------------------------------------
__global__ void out_init_kernel(float* out) {
    int j = threadIdx.x;
    if (j < DIM) out[j] = 0.0f;  // relu output >= 0, so 0 is a valid floor
}

#define POOL_ROWS 100
__global__ void maxpool_kernel(const float* __restrict__ b2, float* __restrict__ out) {
    int col  = threadIdx.x;   // 512 threads
    int row0 = blockIdx.x * POOL_ROWS;
    float bb = b2[col];
    float m = 0.f;
#pragma unroll 4
    for (int r = 0; r < POOL_ROWS; r++) {
        int row = row0 + r;
        if (row >= NNODES) break;
        float v = g_a[(size_t)row * DIM + col] + bb;
        m = fmaxf(m, fmaxf(v, 0.f));
    }
    // all values >= 0 -> int-reinterpreted compare is order-preserving
    atomicMax((int*)out + col, __float_as_int(m));
}

// ---------------------------------------------------------------------------
extern "C" void kernel_launch(void* const* d_in, const int* in_sizes, int n_in,
                              void* d_out, int out_size) {
    const float* X  = (const float*)d_in[0];
    const void*  ei = d_in[1];
    // d_in[2] = edge_attr (unused by GCNConv)
    const float* W1 = (const float*)d_in[3];
    const float* b1 = (const float*)d_in[4];
    const float* W2 = (const float*)d_in[5];
    const float* b2 = (const float*)d_in[6];
    float* out = (float*)d_out;

    // ---- edge index normalization (int32 vs int64 sniff + convert) ----
    flag_init_kernel<<<1, 1>>>();
    dtype_sniff_kernel<<<(NEDGES + 255) / 256, 256>>>((const int*)ei);
    edge_convert_kernel<<<(2 * NEDGES + 255) / 256, 256>>>(ei);

    // ---- normalization + CSR build (reused by both layers) ----
    deg_init_kernel<<<(NNODES + 255) / 256, 256>>>();
    deg_count_kernel<<<(NEDGES + 255) / 256, 256>>>();
    dinv_kernel<<<(NNODES + 255) / 256, 256>>>();
    scan_kernel<<<1, SCAN_T>>>();
    scatter_kernel<<<(NEDGES + 255) / 256, 256>>>();

    dim3 gemm_grid(DIM / 128, (NNODES + 127) / 128);

    // ---- layer 1: h = X @ W1 ; a = A_norm h ----
    gemm512_kernel<0><<<gemm_grid, 256>>>(X, W1, nullptr);
    agg_csr_kernel<<<NNODES, 128>>>();

    // ---- layer 2: h = relu(a + b1) @ W2 ; a = A_norm h ----
    gemm512_kernel<1><<<gemm_grid, 256>>>(nullptr, W2, b1);
    agg_csr_kernel<<<NNODES, 128>>>();

    // ---- global max pool over relu(a + b2) ----
    out_init_kernel<<<1, DIM>>>(out);
    maxpool_kernel<<<(NNODES + POOL_ROWS - 1) / POOL_ROWS, DIM>>>(b2, out);
}

// round 6
// speedup vs baseline: 3.6053x; 1.9598x over previous
#include <cuda_runtime.h>
#include <cstdint>

#define NNODES 20000
#define NEDGES 320000
#define DIM    512

// Scratch (allocation-free rule: __device__ globals)
__device__ float g_h[(size_t)NNODES * DIM];   // GEMM output h = x @ W
__device__ float g_a[(size_t)NNODES * DIM];   // aggregation result
__device__ float g_dinv[NNODES];
__device__ int   g_deg[NNODES];
__device__ int   g_src[NEDGES];
__device__ int   g_dst[NEDGES];
__device__ int   g_is_i32;            // nonzero -> edge_index buffer is int32
__device__ int   g_rowptr[NNODES + 1];
__device__ int   g_cursor[NNODES];
__device__ int   g_csr_src[NEDGES];
__device__ float g_csr_w[NEDGES];
__device__ float g_w1t[DIM * DIM];    // W1 transposed: [N][K]
__device__ float g_w2t[DIM * DIM];    // W2 transposed: [N][K]

__device__ __forceinline__ uint32_t f2tf32(float f) {
    uint32_t r;
    asm("cvt.rna.tf32.f32 %0, %1;" : "=r"(r) : "f"(f));
    return r;
}

// ---------------------------------------------------------------------------
// Edge index normalization: detect int32 vs int64 layout, extract to int
// ---------------------------------------------------------------------------
__global__ void flag_init_kernel() { g_is_i32 = 0; }

__global__ void dtype_sniff_kernel(const int* __restrict__ ei32) {
    int i = blockIdx.x * blockDim.x + threadIdx.x;  // 0 .. E-1
    int acc = 0;
    if (i < NEDGES) acc = ei32[2 * i + 1];
#pragma unroll
    for (int o = 16; o > 0; o >>= 1) acc |= __shfl_xor_sync(0xffffffffu, acc, o);
    if ((threadIdx.x & 31) == 0 && acc != 0) atomicOr(&g_is_i32, 1);
}

__global__ void edge_convert_kernel(const void* __restrict__ ei) {
    int i = blockIdx.x * blockDim.x + threadIdx.x;  // 0 .. 2E-1
    if (i >= 2 * NEDGES) return;
    int v;
    if (g_is_i32) v = ((const int*)ei)[i];
    else          v = (int)((const long long*)ei)[i];
    if (i < NEDGES) g_src[i] = v;
    else            g_dst[i - NEDGES] = v;
}

// ---------------------------------------------------------------------------
// Degree / normalization
// ---------------------------------------------------------------------------
__global__ void deg_init_kernel() {
    int i = blockIdx.x * blockDim.x + threadIdx.x;
    if (i < NNODES) g_deg[i] = 1;  // self-loop
}

__global__ void deg_count_kernel() {
    int e = blockIdx.x * blockDim.x + threadIdx.x;
    if (e < NEDGES) atomicAdd(&g_deg[g_dst[e]], 1);
}

__global__ void dinv_kernel() {
    int i = blockIdx.x * blockDim.x + threadIdx.x;
    if (i < NNODES) g_dinv[i] = rsqrtf((float)g_deg[i]);
}

// ---------------------------------------------------------------------------
// Exclusive prefix scan of in-degree (deg-1) -> rowptr, cursor. 1 block.
// ---------------------------------------------------------------------------
#define SCAN_T 1024
__global__ void scan_kernel() {
    __shared__ int sums[SCAN_T];
    const int CH = (NNODES + SCAN_T - 1) / SCAN_T;  // 20
    int t = threadIdx.x;
    int base = t * CH;
    int local = 0;
#pragma unroll
    for (int i = 0; i < CH; i++) {
        int idx = base + i;
        if (idx < NNODES) local += g_deg[idx] - 1;
    }
    sums[t] = local;
    __syncthreads();
    for (int o = 1; o < SCAN_T; o <<= 1) {
        int v = (t >= o) ? sums[t - o] : 0;
        __syncthreads();
        sums[t] += v;
        __syncthreads();
    }
    int run = (t > 0) ? sums[t - 1] : 0;
#pragma unroll
    for (int i = 0; i < CH; i++) {
        int idx = base + i;
        if (idx < NNODES) {
            g_rowptr[idx] = run;
            g_cursor[idx] = run;
            run += g_deg[idx] - 1;
        }
    }
    if (t == SCAN_T - 1) g_rowptr[NNODES] = sums[SCAN_T - 1];
}

__global__ void scatter_kernel() {
    int e = blockIdx.x * blockDim.x + threadIdx.x;
    if (e >= NEDGES) return;
    int s = g_src[e];
    int d = g_dst[e];
    int pos = atomicAdd(&g_cursor[d], 1);
    g_csr_src[pos] = s;
    g_csr_w[pos] = g_dinv[s] * g_dinv[d];
}

// ---------------------------------------------------------------------------
// Transpose 512x512 W -> Wt (so MMA B operand is [N][K] K-major)
// ---------------------------------------------------------------------------
template <int WHICH>
__global__ void transpose512_kernel(const float* __restrict__ W) {
    __shared__ float t[32][33];
    int bx = blockIdx.x * 32, by = blockIdx.y * 32;
    t[threadIdx.y][threadIdx.x] = W[(by + threadIdx.y) * DIM + bx + threadIdx.x];
    __syncthreads();
    float* o = WHICH ? g_w2t : g_w1t;
    o[(bx + threadIdx.y) * DIM + by + threadIdx.x] = t[threadIdx.x][threadIdx.y];
}

// ---------------------------------------------------------------------------
// Tensor-core GEMM via mma.sync tf32 (baseline PTX, compiles to HMMA):
//   g_h[M,512] = op(A)[M,512] @ W[512,512]
//   MODE 0: A = Aparam (raw),     B = g_w1t
//   MODE 1: A = relu(g_a + bias), B = g_w2t
// CTA 128x128, BK=32, 256 threads = 8 warps (4 M x 2 N), warp tile 32x64.
// Each warp: 2 x 8 m16n8k8 tiles, acc[2][8][4] fp32.
// ---------------------------------------------------------------------------
#define SMS 36  // smem row stride (32 + 4 pad)

template <int MODE>
__global__ void __launch_bounds__(256)
mma_gemm_kernel(const float* __restrict__ Aparam, const float* __restrict__ bias) {
    __shared__ uint32_t As[128 * SMS];
    __shared__ uint32_t Bs[128 * SMS];

    const float* A  = (MODE == 0) ? Aparam : g_a;
    const float* Bt = (MODE == 0) ? g_w1t : g_w2t;

    int tid = threadIdx.x, wid = tid >> 5, lane = tid & 31;
    int row0 = blockIdx.y * 128;
    int col0 = blockIdx.x * 128;
    int wm = (wid & 3) * 32;   // warp M offset in tile
    int wn = (wid >> 2) * 64;  // warp N offset in tile
    int gq = lane >> 2;        // group id (0..7)
    int tq = lane & 3;         // thread-in-group (0..3)

    float acc[2][8][4];
#pragma unroll
    for (int mt = 0; mt < 2; mt++)
#pragma unroll
        for (int nt = 0; nt < 8; nt++)
#pragma unroll
            for (int j = 0; j < 4; j++) acc[mt][nt][j] = 0.f;

    for (int kc = 0; kc < DIM; kc += 32) {
        // ---- load A tile: 128 rows x 32 cols, 4 float4 per thread ----
#pragma unroll
        for (int i = 0; i < 4; i++) {
            int idx = tid + 256 * i;
            int r = idx >> 3, c4 = idx & 7;
            int grow = row0 + r;
            float4 v = make_float4(0.f, 0.f, 0.f, 0.f);
            if (grow < NNODES)
                v = *(const float4*)&A[(size_t)grow * DIM + kc + c4 * 4];
            if (MODE == 1) {
                float4 bb = *(const float4*)&bias[kc + c4 * 4];
                v.x = fmaxf(v.x + bb.x, 0.f);
                v.y = fmaxf(v.y + bb.y, 0.f);
                v.z = fmaxf(v.z + bb.z, 0.f);
                v.w = fmaxf(v.w + bb.w, 0.f);
            }
            uint4 tv = make_uint4(f2tf32(v.x), f2tf32(v.y), f2tf32(v.z), f2tf32(v.w));
            *(uint4*)&As[r * SMS + c4 * 4] = tv;
        }
        // ---- load B tile: rows n = col0..+127 of Wt[N][K] ----
#pragma unroll
        for (int i = 0; i < 4; i++) {
            int idx = tid + 256 * i;
            int r = idx >> 3, c4 = idx & 7;
            float4 v = *(const float4*)&Bt[(size_t)(col0 + r) * DIM + kc + c4 * 4];
            uint4 tv = make_uint4(f2tf32(v.x), f2tf32(v.y), f2tf32(v.z), f2tf32(v.w));
            *(uint4*)&Bs[r * SMS + c4 * 4] = tv;
        }
        __syncthreads();

#pragma unroll
        for (int ks = 0; ks < 4; ks++) {
            int k0 = ks * 8;
            uint32_t af[2][4], bf[8][2];
#pragma unroll
            for (int mt = 0; mt < 2; mt++) {
                int r = wm + mt * 16 + gq;
                af[mt][0] = As[r * SMS + k0 + tq];
                af[mt][1] = As[(r + 8) * SMS + k0 + tq];
                af[mt][2] = As[r * SMS + k0 + tq + 4];
                af[mt][3] = As[(r + 8) * SMS + k0 + tq + 4];
            }
#pragma unroll
            for (int nt = 0; nt < 8; nt++) {
                int n = wn + nt * 8 + gq;
                bf[nt][0] = Bs[n * SMS + k0 + tq];
                bf[nt][1] = Bs[n * SMS + k0 + tq + 4];
            }
#pragma unroll
            for (int mt = 0; mt < 2; mt++)
#pragma unroll
                for (int nt = 0; nt < 8; nt++) {
                    asm volatile(
                        "mma.sync.aligned.m16n8k8.row.col.f32.tf32.tf32.f32 "
                        "{%0,%1,%2,%3}, {%4,%5,%6,%7}, {%8,%9}, {%0,%1,%2,%3};"
                        : "+f"(acc[mt][nt][0]), "+f"(acc[mt][nt][1]),
                          "+f"(acc[mt][nt][2]), "+f"(acc[mt][nt][3])
                        : "r"(af[mt][0]), "r"(af[mt][1]),
                          "r"(af[mt][2]), "r"(af[mt][3]),
                          "r"(bf[nt][0]), "r"(bf[nt][1]));
                }
        }
        __syncthreads();
    }

    // ---- epilogue: fragments -> g_h ----
#pragma unroll
    for (int mt = 0; mt < 2; mt++) {
        int r0 = row0 + wm + mt * 16 + gq;
#pragma unroll
        for (int nt = 0; nt < 8; nt++) {
            int c = col0 + wn + nt * 8 + tq * 2;
            if (r0 < NNODES)
                *(float2*)&g_h[(size_t)r0 * DIM + c] =
                    make_float2(acc[mt][nt][0], acc[mt][nt][1]);
            if (r0 + 8 < NNODES)
                *(float2*)&g_h[(size_t)(r0 + 8) * DIM + c] =
                    make_float2(acc[mt][nt][2], acc[mt][nt][3]);
        }
    }
}

// ---------------------------------------------------------------------------
// CSR aggregation (atomic-free, self-loop fused):
//   a[d,:] = dinv[d]^2 * h[d,:] + sum_{e: dst=d} w_e * h[src_e,:]
// ---------------------------------------------------------------------------
__global__ void __launch_bounds__(128)
agg_csr_kernel() {
    int d = blockIdx.x;
    int t = threadIdx.x;  // 0..127 -> float4 column
    const float4* __restrict__ h4 = (const float4*)g_h;

    float dv = g_dinv[d];
    float4 acc = h4[(size_t)d * 128 + t];
    float ws = dv * dv;
    acc.x *= ws; acc.y *= ws; acc.z *= ws; acc.w *= ws;

    int j   = g_rowptr[d];
    int end = g_rowptr[d + 1];

    for (; j + 4 <= end; j += 4) {
        int   s0 = g_csr_src[j],     s1 = g_csr_src[j + 1];
        int   s2 = g_csr_src[j + 2], s3 = g_csr_src[j + 3];
        float w0 = g_csr_w[j],       w1 = g_csr_w[j + 1];
        float w2 = g_csr_w[j + 2],   w3 = g_csr_w[j + 3];
        float4 v0 = h4[(size_t)s0 * 128 + t];
        float4 v1 = h4[(size_t)s1 * 128 + t];
        float4 v2 = h4[(size_t)s2 * 128 + t];
        float4 v3 = h4[(size_t)s3 * 128 + t];
        acc.x += v0.x * w0 + v1.x * w1 + v2.x * w2 + v3.x * w3;
        acc.y += v0.y * w0 + v1.y * w1 + v2.y * w2 + v3.y * w3;
        acc.z += v0.z * w0 + v1.z * w1 + v2.z * w2 + v3.z * w3;
        acc.w += v0.w * w0 + v1.w * w1 + v2.w * w2 + v3.w * w3;
    }
    for (; j < end; j++) {
        int   s = g_csr_src[j];
        float w = g_csr_w[j];
        float4 v = h4[(size_t)s * 128 + t];
        acc.x += v.x * w; acc.y += v.y * w;
        acc.z += v.z * w; acc.w += v.w * w;
    }

    ((float4*)g_a)[(size_t)d * 128 + t] = acc;
}

// ---------------------------------------------------------------------------
// Output init + max pool: out[j] = max_i relu(a[i,j] + b2[j])
// ---------------------------------------------------------------------------
__global__ void out_init_kernel(float* out) {
    int j = threadIdx.x;
    if (j < DIM) out[j] = 0.0f;  // relu output >= 0, so 0 is a valid floor
}

#define POOL_ROWS 100
__global__ void maxpool_kernel(const float* __restrict__ b2, float* __restrict__ out) {
    int col  = threadIdx.x;   // 512 threads
    int row0 = blockIdx.x * POOL_ROWS;
    float bb = b2[col];
    float m = 0.f;
#pragma unroll 4
    for (int r = 0; r < POOL_ROWS; r++) {
        int row = row0 + r;
        if (row >= NNODES) break;
        float v = g_a[(size_t)row * DIM + col] + bb;
        m = fmaxf(m, fmaxf(v, 0.f));
    }
    atomicMax((int*)out + col, __float_as_int(m));
}

// ---------------------------------------------------------------------------
extern "C" void kernel_launch(void* const* d_in, const int* in_sizes, int n_in,
                              void* d_out, int out_size) {
    const float* X  = (const float*)d_in[0];
    const void*  ei = d_in[1];
    // d_in[2] = edge_attr (unused by GCNConv)
    const float* W1 = (const float*)d_in[3];
    const float* b1 = (const float*)d_in[4];
    const float* W2 = (const float*)d_in[5];
    const float* b2 = (const float*)d_in[6];
    float* out = (float*)d_out;

    // ---- edge index normalization (int32 vs int64 sniff + convert) ----
    flag_init_kernel<<<1, 1>>>();
    dtype_sniff_kernel<<<(NEDGES + 255) / 256, 256>>>((const int*)ei);
    edge_convert_kernel<<<(2 * NEDGES + 255) / 256, 256>>>(ei);

    // ---- normalization + CSR build ----
    deg_init_kernel<<<(NNODES + 255) / 256, 256>>>();
    deg_count_kernel<<<(NEDGES + 255) / 256, 256>>>();
    dinv_kernel<<<(NNODES + 255) / 256, 256>>>();
    scan_kernel<<<1, SCAN_T>>>();
    scatter_kernel<<<(NEDGES + 255) / 256, 256>>>();

    // ---- weight transposes for MMA B operands ----
    dim3 tgrid(16, 16), tblk(32, 32);
    transpose512_kernel<0><<<tgrid, tblk>>>(W1);
    transpose512_kernel<1><<<tgrid, tblk>>>(W2);

    dim3 gemm_grid(DIM / 128, (NNODES + 127) / 128);  // (4, 157)

    // ---- layer 1: h = X @ W1 ; a = A_norm h ----
    mma_gemm_kernel<0><<<gemm_grid, 256>>>(X, nullptr);
    agg_csr_kernel<<<NNODES, 128>>>();

    // ---- layer 2: h = relu(a + b1) @ W2 ; a = A_norm h ----
    mma_gemm_kernel<1><<<gemm_grid, 256>>>(nullptr, b1);
    agg_csr_kernel<<<NNODES, 128>>>();

    // ---- global max pool over relu(a + b2) ----
    out_init_kernel<<<1, DIM>>>(out);
    maxpool_kernel<<<(NNODES + POOL_ROWS - 1) / POOL_ROWS, DIM>>>(b2, out);
}